// round 14
// baseline (speedup 1.0000x reference)
#include <cuda_runtime.h>
#include <cuda_fp16.h>
#include <cstdint>

#define HIDDEN 2048
#define SEQ    2048
#define BATCH  2
#define NHEADS 16
#define HDIM   128
#define MROWS  (BATCH * SEQ)   // 4096

// ---------- scratch (all fp16) ----------
__device__ __half g_xh[MROWS * HIDDEN], g_xl[MROWS * HIDDEN];
__device__ __half g_oh[MROWS * HIDDEN];
__device__ __half g_qbh[MROWS * HIDDEN], g_qbl[MROWS * HIDDEN];
__device__ __half g_kbh[MROWS * HIDDEN], g_kbl[MROWS * HIDDEN];
__device__ __half g_vf[MROWS * HIDDEN];
__device__ __half g_wqf[HIDDEN * HIDDEN], g_wkf[HIDDEN * HIDDEN];
__device__ __half g_wvf[HIDDEN * HIDDEN], g_wof[HIDDEN * HIDDEN];

// ---------- PTX wrappers (sm_80/90-era, valid on compute_103) ----------
__device__ __forceinline__ uint32_t smem_u32(const void* p) {
    uint32_t a;
    asm("{ .reg .u64 t; cvta.to.shared.u64 t, %1; cvt.u32.u64 %0, t; }" : "=r"(a) : "l"(p));
    return a;
}
__device__ __forceinline__ void cp16(uint32_t sdst, const void* gsrc) {
    asm volatile("cp.async.cg.shared.global [%0], [%1], 16;" :: "r"(sdst), "l"(gsrc) : "memory");
}
#define CP_COMMIT() asm volatile("cp.async.commit_group;" ::: "memory")
#define CP_WAIT1()  asm volatile("cp.async.wait_group 1;" ::: "memory")
#define CP_WAIT2()  asm volatile("cp.async.wait_group 2;" ::: "memory")

__device__ __forceinline__ void ldsm_x4(uint32_t (&r)[4], uint32_t addr) {
    asm volatile("ldmatrix.sync.aligned.m8n8.x4.shared.b16 {%0,%1,%2,%3}, [%4];"
                 : "=r"(r[0]), "=r"(r[1]), "=r"(r[2]), "=r"(r[3]) : "r"(addr));
}
__device__ __forceinline__ void ldsm_x4_t(uint32_t (&r)[4], uint32_t addr) {
    asm volatile("ldmatrix.sync.aligned.m8n8.x4.trans.shared.b16 {%0,%1,%2,%3}, [%4];"
                 : "=r"(r[0]), "=r"(r[1]), "=r"(r[2]), "=r"(r[3]) : "r"(addr));
}
__device__ __forceinline__ void mma16816h(float (&d)[4], const uint32_t (&a)[4],
                                          uint32_t b0, uint32_t b1) {
    asm volatile(
        "mma.sync.aligned.m16n8k16.row.col.f32.f16.f16.f32 "
        "{%0,%1,%2,%3}, {%4,%5,%6,%7}, {%8,%9}, {%0,%1,%2,%3};"
        : "+f"(d[0]), "+f"(d[1]), "+f"(d[2]), "+f"(d[3])
        : "r"(a[0]), "r"(a[1]), "r"(a[2]), "r"(a[3]), "r"(b0), "r"(b1));
}
__device__ __forceinline__ uint32_t pack_f16x2(float lo, float hi) {
    __half2 h = __float22half2_rn(make_float2(lo, hi));
    return *(uint32_t*)&h;
}

// ---------- fused fp32 -> fp16 conversions ----------
__global__ __launch_bounds__(256)
void cvt_all(const float4* __restrict__ x,  const float4* __restrict__ wq,
             const float4* __restrict__ wk, const float4* __restrict__ wv,
             const float4* __restrict__ wo,
             __half2* xh, __half2* xl,
             __half2* wqf, __half2* wkf, __half2* wvf, __half2* wof)
{
    int bid = blockIdx.x;
    if (bid < 8192) {
        size_t i = (size_t)bid * 256 + threadIdx.x;
        float4 v = x[i];
        __half hx = __float2half_rn(v.x), hy = __float2half_rn(v.y);
        __half hz = __float2half_rn(v.z), hw = __float2half_rn(v.w);
        xh[2 * i]     = __halves2half2(hx, hy);
        xh[2 * i + 1] = __halves2half2(hz, hw);
        xl[2 * i]     = __halves2half2(__float2half_rn(v.x - __half2float(hx)),
                                       __float2half_rn(v.y - __half2float(hy)));
        xl[2 * i + 1] = __halves2half2(__float2half_rn(v.z - __half2float(hz)),
                                       __float2half_rn(v.w - __half2float(hw)));
        return;
    }
    const float4* src; __half2* dst; int base;
    if      (bid < 12288) { src = wq; dst = wqf; base = bid - 8192; }
    else if (bid < 16384) { src = wk; dst = wkf; base = bid - 12288; }
    else if (bid < 20480) { src = wv; dst = wvf; base = bid - 16384; }
    else                  { src = wo; dst = wof; base = bid - 20480; }
    size_t i = (size_t)base * 256 + threadIdx.x;
    float4 v = src[i];
    dst[2 * i]     = __float22half2_rn(make_float2(v.x, v.y));
    dst[2 * i + 1] = __float22half2_rn(make_float2(v.z, v.w));
}

// =====================================================================
// fp16 HMMA GEMM: C = (Ah [+ Al]) @ B^T.  onepass_mask bit z => skip Al.
// 256x128 CTA tile, 8 warps (4m x 2n), WARP TILE 64x64, BK=32.
// 64B rows + XOR swizzle. 12 ldsm per 64 HMMA (was 8 per 32).
// Group-paired pipeline: 4 stages = 2 groups of 2 chunks, 1 barrier/2 chunks.
// 1 CTA/SM (160KB smem), 256 regs/thread available.
// =====================================================================
#define BK       32
#define NKCH     (HIDDEN / BK)          // 64
#define NGRP     (NKCH / 2)             // 32
#define ROWB     64
#define TILE_AB  (256 * ROWB)           // 16384 (Ah or Al)
#define TILE_BB  (128 * ROWB)           // 8192  (B)
#define OFF_AL   TILE_AB
#define OFF_B    (2 * TILE_AB)
#define STAGE_B  (2 * TILE_AB + TILE_BB)  // 40960
#define GEMM_SMEM (4 * STAGE_B)           // 163840

__global__ __launch_bounds__(256, 1)
void gemm2(const __half* __restrict__ Ah, const __half* __restrict__ Al,
           const __half* __restrict__ B0, const __half* __restrict__ B1,
           const __half* __restrict__ B2,
           __half* __restrict__ Ch0, __half* __restrict__ Cl0,
           __half* __restrict__ Ch1, __half* __restrict__ Cl1,
           __half* __restrict__ Cf2,
           float* __restrict__ C,
           int onepass_mask,
           int M, int N, int K)
{
    extern __shared__ __align__(128) char smem[];
    const uint32_t sbase = smem_u32(smem);
    const int tid  = threadIdx.x;
    const int wid  = tid >> 5;
    const int lane = tid & 31;
    const int wm   = wid & 3;          // 64-row slab
    const int wn   = wid >> 2;         // 64-col slab
    const int z    = blockIdx.z;
    const bool two = !((onepass_mask >> z) & 1);
    const size_t brow = (size_t)blockIdx.y * 256;
    const size_t bcol = (size_t)blockIdx.x * 128;

    const __half* Bsel = (z == 0) ? B0 : (z == 1) ? B1 : B2;

    // cp.async slots: A row = tid (all 4 segs), B row = tid>>1 (2 segs)
    const int rowA  = tid;
    const int mskA_ = (rowA >> 1) & 3;
    uint32_t soffA[4];
#pragma unroll
    for (int i = 0; i < 4; ++i)
        soffA[i] = (uint32_t)(rowA * ROWB + ((i ^ mskA_) << 4));
    const int rowBc = tid >> 1;
    const int spB   = (tid & 1) * 2;
    const int mskB_ = (rowBc >> 1) & 3;
    const uint32_t soffB0 = (uint32_t)(rowBc * ROWB + ((spB     ^ mskB_) << 4));
    const uint32_t soffB1 = (uint32_t)(rowBc * ROWB + (((spB+1) ^ mskB_) << 4));

    const size_t Kb = (size_t)K * 2;
    const char* pAh = (const char*)Ah   + (brow + rowA) * Kb;
    const char* pAl = (const char*)Al   + (brow + rowA) * Kb;
    const char* pB  = (const char*)Bsel + (bcol + rowBc) * Kb + spB * 16;

#define LOAD_CHUNK(c, s) do {                                        \
        uint32_t sb_ = sbase + (uint32_t)(s) * STAGE_B;              \
        size_t g_ = (size_t)(c) * 64;                                \
        _Pragma("unroll")                                            \
        for (int i_ = 0; i_ < 4; ++i_)                               \
            cp16(sb_ + soffA[i_], pAh + g_ + i_ * 16);               \
        if (two) {                                                   \
            _Pragma("unroll")                                        \
            for (int i_ = 0; i_ < 4; ++i_)                           \
                cp16(sb_ + OFF_AL + soffA[i_], pAl + g_ + i_ * 16);  \
        }                                                            \
        cp16(sb_ + OFF_B + soffB0, pB + g_);                         \
        cp16(sb_ + OFF_B + soffB1, pB + g_ + 16);                    \
    } while (0)

    // ldsm addressing
    const int rA    = wm * 64 + (lane & 15);
    const int aSeg  = lane >> 4;
    const int maskA = (rA >> 1) & 3;       // invariant under +16
    const int rB    = wn * 64 + ((lane >> 4) << 3) + (lane & 7);
    const int bSeg  = (lane >> 3) & 1;
    const int maskB = (rB >> 1) & 3;

    float acc[4][8][4];
#pragma unroll
    for (int mt = 0; mt < 4; ++mt)
#pragma unroll
        for (int nt = 0; nt < 8; ++nt)
#pragma unroll
            for (int q = 0; q < 4; ++q) acc[mt][nt][q] = 0.f;

    LOAD_CHUNK(0, 0);
    LOAD_CHUNK(1, 1);
    CP_COMMIT();

    for (int g = 0; g < NGRP; ++g) {
        __syncthreads();                 // all warps done with group g-1
        if (g + 1 < NGRP) {
            LOAD_CHUNK(2 * g + 2, (2 * g + 2) & 3);
            LOAD_CHUNK(2 * g + 3, (2 * g + 3) & 3);
        }
        CP_COMMIT();
        CP_WAIT1();                      // group g's data complete

#pragma unroll
        for (int u = 0; u < 2; ++u) {
            const uint32_t sb = sbase + (uint32_t)((2 * g + u) & 3) * STAGE_B;

#pragma unroll
            for (int k16 = 0; k16 < 2; ++k16) {
                uint32_t ah[4][4];
#pragma unroll
                for (int mt = 0; mt < 4; ++mt) {
                    uint32_t byteoff = (uint32_t)((rA + mt * 16) * ROWB +
                                                  ((2 * k16 + aSeg) ^ maskA) * 16);
                    ldsm_x4(ah[mt], sb + byteoff);
                }
                uint32_t bh[4][4];
#pragma unroll
                for (int np = 0; np < 4; ++np) {
                    uint32_t byteoff = (uint32_t)((rB + np * 16) * ROWB +
                                                  ((2 * k16 + bSeg) ^ maskB) * 16);
                    ldsm_x4(bh[np], sb + OFF_B + byteoff);
                }
                // pass 1: Ah * B
#pragma unroll
                for (int np = 0; np < 4; ++np)
#pragma unroll
                    for (int mt = 0; mt < 4; ++mt) {
                        mma16816h(acc[mt][2 * np + 0], ah[mt], bh[np][0], bh[np][1]);
                        mma16816h(acc[mt][2 * np + 1], ah[mt], bh[np][2], bh[np][3]);
                    }
                // pass 2: Al * B (al loaded per-mt to cap registers)
                if (two) {
#pragma unroll
                    for (int mt = 0; mt < 4; ++mt) {
                        uint32_t al[4];
                        uint32_t byteoff = (uint32_t)((rA + mt * 16) * ROWB +
                                                      ((2 * k16 + aSeg) ^ maskA) * 16);
                        ldsm_x4(al, sb + OFF_AL + byteoff);
#pragma unroll
                        for (int np = 0; np < 4; ++np) {
                            mma16816h(acc[mt][2 * np + 0], al, bh[np][0], bh[np][1]);
                            mma16816h(acc[mt][2 * np + 1], al, bh[np][2], bh[np][3]);
                        }
                    }
                }
            }
        }
    }

    __half* Ch = (z == 0) ? Ch0 : Ch1;
    __half* Cl = (z == 0) ? Cl0 : Cl1;
#pragma unroll
    for (int mt = 0; mt < 4; ++mt) {
        size_t r0 = brow + wm * 64 + mt * 16 + (lane >> 2);
#pragma unroll
        for (int nt = 0; nt < 8; ++nt) {
            size_t col = bcol + wn * 64 + nt * 8 + 2 * (lane & 3);
            if (C) {
                *(float2*)&C[r0 * (size_t)N + col]       = make_float2(acc[mt][nt][0], acc[mt][nt][1]);
                *(float2*)&C[(r0 + 8) * (size_t)N + col] = make_float2(acc[mt][nt][2], acc[mt][nt][3]);
            } else if (z == 2) {
#pragma unroll
                for (int hf = 0; hf < 2; ++hf) {
                    size_t idx = (r0 + 8 * hf) * (size_t)N + col;
                    *(__half2*)&Cf2[idx] = __float22half2_rn(
                        make_float2(acc[mt][nt][2 * hf], acc[mt][nt][2 * hf + 1]));
                }
            } else {
#pragma unroll
                for (int hf = 0; hf < 2; ++hf) {
                    float v0 = acc[mt][nt][2 * hf + 0];
                    float v1 = acc[mt][nt][2 * hf + 1];
                    __half h0 = __float2half_rn(v0);
                    __half h1 = __float2half_rn(v1);
                    size_t idx = (r0 + 8 * hf) * (size_t)N + col;
                    *(__half2*)&Ch[idx] = __halves2half2(h0, h1);
                    *(__half2*)&Cl[idx] = __halves2half2(
                        __float2half_rn(v0 - __half2float(h0)),
                        __float2half_rn(v1 - __half2float(h1)));
                }
            }
        }
    }
}

// =====================================================================
// FlashAttention-2 on fp16 HMMA (R13: scores -> softmax -> PV, Q h+l preloaded).
// =====================================================================
#define QT        128
#define SROW      272
#define AQL_OFF   34816
#define AST_OFF   69632
#define AST_SZ    52224
#define AKL_OFF   17408
#define AV_OFF    34816
#define ATTN_SMEM 226304
#define NKT       (SEQ / 64)   // 32

__global__ __launch_bounds__(256, 1)
void attn_mma(const __half* __restrict__ Qh, const __half* __restrict__ Ql,
              const __half* __restrict__ Kh, const __half* __restrict__ Kl,
              const __half* __restrict__ Vf,
              __half* __restrict__ Oh)
{
    extern __shared__ __align__(128) char smem[];
    const uint32_t sb = smem_u32(smem);
    const int tid  = threadIdx.x;
    const int wid  = tid >> 5;
    const int lane = tid & 31;
    const int b    = blockIdx.x >> 4;
    const int h    = blockIdx.x & 15;
    const int qt   = blockIdx.y;

    const float scale = 0.08838834764831843f;   // 1/sqrt(128)
    const size_t hoff  = (size_t)h * HDIM;
    const size_t qrow0 = (size_t)b * SEQ + (size_t)qt * QT;
    const size_t krow0 = (size_t)b * SEQ;

#pragma unroll
    for (int it = 0; it < 8; ++it) {
        int idx = it * 256 + tid;
        int r   = idx >> 4;
        int ch  = idx & 15;
        size_t g = ((qrow0 + r) * HIDDEN + hoff + ch * 8) * 2;
        uint32_t d = sb + (uint32_t)(r * SROW + ch * 16);
        cp16(d,           (const char*)Qh + g);
        cp16(d + AQL_OFF, (const char*)Ql + g);
    }
#define LOAD_KV(c, s) do {                                                     \
        uint32_t st_ = sb + AST_OFF + (uint32_t)(s) * AST_SZ;                  \
        _Pragma("unroll")                                                      \
        for (int it_ = 0; it_ < 4; ++it_) {                                    \
            int idx_ = it_ * 256 + tid;                                        \
            int r_  = idx_ >> 4;                                               \
            int ch_ = idx_ & 15;                                               \
            size_t g_ = ((krow0 + (size_t)(c) * 64 + r_) * HIDDEN + hoff + ch_ * 8) * 2; \
            uint32_t d_ = st_ + (uint32_t)(r_ * SROW + ch_ * 16);              \
            cp16(d_,           (const char*)Kh + g_);                          \
            cp16(d_ + AKL_OFF, (const char*)Kl + g_);                          \
            cp16(d_ + AV_OFF,  (const char*)Vf + g_);                          \
        }                                                                      \
    } while (0)

    LOAD_KV(0, 0); CP_COMMIT();
    LOAD_KV(1, 1); CP_COMMIT();
    CP_WAIT1();
    __syncthreads();

    // ---- preload Q hi AND lo A-frags ----
    const int arow = lane & 15;
    const int aseg = lane >> 4;
    const uint32_t qbase  = sb + (uint32_t)((wid * 16 + arow) * SROW + aseg * 16);
    const uint32_t qlbase = qbase + AQL_OFF;
    uint32_t qh[8][4], ql[8][4];
#pragma unroll
    for (int ks = 0; ks < 8; ++ks) {
        ldsm_x4(qh[ks], qbase  + ks * 32);
        ldsm_x4(ql[ks], qlbase + ks * 32);
    }

    float Oacc[16][4];
#pragma unroll
    for (int nt = 0; nt < 16; ++nt)
#pragma unroll
        for (int q = 0; q < 4; ++q) Oacc[nt][q] = 0.f;
    float m0 = -1e30f, m1 = -1e30f, l0 = 0.f, l1 = 0.f;

    const int brow = ((lane >> 4) << 3) + (lane & 7);
    const int bseg = (lane >> 3) & 1;

    int stage = 0;
    for (int kt = 0; kt < NKT; ++kt) {
        __syncthreads();
        if (kt + 2 < NKT) {
            int s2 = stage + 2; if (s2 >= 3) s2 -= 3;
            LOAD_KV(kt + 2, s2);
        }
        CP_COMMIT();
        CP_WAIT2();

        const uint32_t st = sb + AST_OFF + (uint32_t)stage * AST_SZ;

        float S[8][4];
#pragma unroll
        for (int nt = 0; nt < 8; ++nt)
#pragma unroll
            for (int q = 0; q < 4; ++q) S[nt][q] = 0.f;

#pragma unroll
        for (int ks = 0; ks < 8; ++ks) {
            uint32_t koff = (uint32_t)(brow * SROW + ks * 32 + bseg * 16);
            uint32_t kh4[4][4];
#pragma unroll
            for (int p = 0; p < 4; ++p) ldsm_x4(kh4[p], st + p * (16 * SROW) + koff);
#pragma unroll
            for (int p = 0; p < 4; ++p) {
                mma16816h(S[2 * p + 0], qh[ks], kh4[p][0], kh4[p][1]);
                mma16816h(S[2 * p + 1], qh[ks], kh4[p][2], kh4[p][3]);
            }
#pragma unroll
            for (int p = 0; p < 4; ++p) {
                mma16816h(S[2 * p + 0], ql[ks], kh4[p][0], kh4[p][1]);
                mma16816h(S[2 * p + 1], ql[ks], kh4[p][2], kh4[p][3]);
            }
#pragma unroll
            for (int p = 0; p < 4; ++p) {
                uint32_t kl4[4];
                ldsm_x4(kl4, st + AKL_OFF + p * (16 * SROW) + koff);
                mma16816h(S[2 * p + 0], qh[ks], kl4[0], kl4[1]);
                mma16816h(S[2 * p + 1], qh[ks], kl4[2], kl4[3]);
            }
        }

        // ---- online softmax ----
        float mx0 = -1e30f, mx1 = -1e30f;
#pragma unroll
        for (int nt = 0; nt < 8; ++nt) {
            mx0 = fmaxf(mx0, fmaxf(S[nt][0], S[nt][1]));
            mx1 = fmaxf(mx1, fmaxf(S[nt][2], S[nt][3]));
        }
        mx0 = fmaxf(mx0, __shfl_xor_sync(0xffffffffu, mx0, 1));
        mx0 = fmaxf(mx0, __shfl_xor_sync(0xffffffffu, mx0, 2));
        mx1 = fmaxf(mx1, __shfl_xor_sync(0xffffffffu, mx1, 1));
        mx1 = fmaxf(mx1, __shfl_xor_sync(0xffffffffu, mx1, 2));
        float mn0 = fmaxf(m0, mx0), mn1 = fmaxf(m1, mx1);
        float cf0 = __expf(scale * (m0 - mn0));
        float cf1 = __expf(scale * (m1 - mn1));
        m0 = mn0; m1 = mn1;
        float bb0 = -scale * mn0, bb1 = -scale * mn1;
        float rs0 = 0.f, rs1 = 0.f;
#pragma unroll
        for (int nt = 0; nt < 8; ++nt) {
            S[nt][0] = __expf(fmaf(S[nt][0], scale, bb0));
            S[nt][1] = __expf(fmaf(S[nt][1], scale, bb0));
            S[nt][2] = __expf(fmaf(S[nt][2], scale, bb1));
            S[nt][3] = __expf(fmaf(S[nt][3], scale, bb1));
            rs0 += S[nt][0] + S[nt][1];
            rs1 += S[nt][2] + S[nt][3];
        }
        rs0 += __shfl_xor_sync(0xffffffffu, rs0, 1);
        rs0 += __shfl_xor_sync(0xffffffffu, rs0, 2);
        rs1 += __shfl_xor_sync(0xffffffffu, rs1, 1);
        rs1 += __shfl_xor_sync(0xffffffffu, rs1, 2);
        l0 = l0 * cf0 + rs0;
        l1 = l1 * cf1 + rs1;

#pragma unroll
        for (int nt = 0; nt < 16; ++nt) {
            Oacc[nt][0] *= cf0; Oacc[nt][1] *= cf0;
            Oacc[nt][2] *= cf1; Oacc[nt][3] *= cf1;
        }
        uint32_t pa[4][4];
#pragma unroll
        for (int t = 0; t < 4; ++t) {
            pa[t][0] = pack_f16x2(S[2 * t][0],     S[2 * t][1]);
            pa[t][1] = pack_f16x2(S[2 * t][2],     S[2 * t][3]);
            pa[t][2] = pack_f16x2(S[2 * t + 1][0], S[2 * t + 1][1]);
            pa[t][3] = pack_f16x2(S[2 * t + 1][2], S[2 * t + 1][3]);
        }

        // ---- PV (fp16 x fp16 -> fp32) ----
        const uint32_t vbase = st + AV_OFF;
#pragma unroll
        for (int t = 0; t < 4; ++t) {
            uint32_t rowoff = vbase + (uint32_t)((t * 16 + (lane & 15)) * SROW + (lane >> 4) * 16);
#pragma unroll
            for (int dp = 0; dp < 8; ++dp) {
                uint32_t vb[4];
                ldsm_x4_t(vb, rowoff + dp * 32);
                mma16816h(Oacc[2 * dp + 0], pa[t], vb[0], vb[1]);
                mma16816h(Oacc[2 * dp + 1], pa[t], vb[2], vb[3]);
            }
        }
        stage = (stage == 2) ? 0 : stage + 1;
    }

    // ---- epilogue: normalize, write single fp16 O ----
    float inv0 = 1.0f / l0, inv1 = 1.0f / l1;
    int r = wid * 16 + (lane >> 2);
    size_t g0 = (qrow0 + r) * HIDDEN + hoff;
    size_t g1 = g0 + 8 * HIDDEN;
#pragma unroll
    for (int nt = 0; nt < 16; ++nt) {
        int col = nt * 8 + 2 * (lane & 3);
        *(__half2*)&Oh[g0 + col] = __float22half2_rn(
            make_float2(Oacc[nt][0] * inv0, Oacc[nt][1] * inv0));
        *(__half2*)&Oh[g1 + col] = __float22half2_rn(
            make_float2(Oacc[nt][2] * inv1, Oacc[nt][3] * inv1));
    }
}

// =====================================================================
extern "C" void kernel_launch(void* const* d_in, const int* in_sizes, int n_in,
                              void* d_out, int out_size)
{
    const float* x  = (const float*)d_in[0];
    const float* wq = (const float*)d_in[1];
    const float* wk = (const float*)d_in[2];
    const float* wv = (const float*)d_in[3];
    const float* wo = (const float*)d_in[4];
    float* out = (float*)d_out;

    __half *xh, *xl, *oh, *qbh, *qbl, *kbh, *kbl, *vf;
    __half *wqf, *wkf, *wvf, *wof;
    cudaGetSymbolAddress((void**)&xh, g_xh);   cudaGetSymbolAddress((void**)&xl, g_xl);
    cudaGetSymbolAddress((void**)&oh, g_oh);
    cudaGetSymbolAddress((void**)&qbh, g_qbh); cudaGetSymbolAddress((void**)&qbl, g_qbl);
    cudaGetSymbolAddress((void**)&kbh, g_kbh); cudaGetSymbolAddress((void**)&kbl, g_kbl);
    cudaGetSymbolAddress((void**)&vf, g_vf);
    cudaGetSymbolAddress((void**)&wqf, g_wqf); cudaGetSymbolAddress((void**)&wkf, g_wkf);
    cudaGetSymbolAddress((void**)&wvf, g_wvf); cudaGetSymbolAddress((void**)&wof, g_wof);

    const int M = MROWS;   // 4096

    cvt_all<<<24576, 256>>>((const float4*)x, (const float4*)wq, (const float4*)wk,
                            (const float4*)wv, (const float4*)wo,
                            (__half2*)xh, (__half2*)xl,
                            (__half2*)wqf, (__half2*)wkf, (__half2*)wvf, (__half2*)wof);

    cudaFuncSetAttribute(gemm2, cudaFuncAttributeMaxDynamicSharedMemorySize, GEMM_SMEM);
    // fused QKV: z=0 -> Q (2-pass, h/l out), z=1 -> K (2-pass, h/l out),
    //            z=2 -> V (1-pass, single fp16 out)   [R11/R13 numerics]
    gemm2<<<dim3(HIDDEN / 128, M / 256, 3), 256, GEMM_SMEM>>>(
        xh, xl, wqf, wkf, wvf, qbh, qbl, kbh, kbl, vf, nullptr,
        /*onepass_mask=*/0b100, M, HIDDEN, HIDDEN);

    cudaFuncSetAttribute(attn_mma, cudaFuncAttributeMaxDynamicSharedMemorySize, ATTN_SMEM);
    attn_mma<<<dim3(BATCH * NHEADS, SEQ / QT), 256, ATTN_SMEM>>>(qbh, qbl, kbh, kbl, vf, oh);

    // output projection: 1-pass (O single fp16), fp32 out
    gemm2<<<dim3(HIDDEN / 128, M / 256, 1), 256, GEMM_SMEM>>>(
        oh, oh, wof, wof, wof, nullptr, nullptr, nullptr, nullptr, nullptr, out,
        /*onepass_mask=*/0b001, M, HIDDEN, HIDDEN);
}

// round 16
// speedup vs baseline: 1.2209x; 1.2209x over previous
#include <cuda_runtime.h>
#include <cuda_fp16.h>
#include <cstdint>

#define HIDDEN 2048
#define SEQ    2048
#define BATCH  2
#define NHEADS 16
#define HDIM   128
#define MROWS  (BATCH * SEQ)   // 4096

// ---------- scratch (all fp16) ----------
__device__ __half g_xh[MROWS * HIDDEN], g_xl[MROWS * HIDDEN];
__device__ __half g_oh[MROWS * HIDDEN];
__device__ __half g_qbh[MROWS * HIDDEN], g_qbl[MROWS * HIDDEN];
__device__ __half g_kbh[MROWS * HIDDEN], g_kbl[MROWS * HIDDEN];
__device__ __half g_vf[MROWS * HIDDEN];
__device__ __half g_wqf[HIDDEN * HIDDEN], g_wkf[HIDDEN * HIDDEN];
__device__ __half g_wvf[HIDDEN * HIDDEN], g_wof[HIDDEN * HIDDEN];

// ---------- PTX wrappers (sm_80/90-era, valid on compute_103) ----------
__device__ __forceinline__ uint32_t smem_u32(const void* p) {
    uint32_t a;
    asm("{ .reg .u64 t; cvta.to.shared.u64 t, %1; cvt.u32.u64 %0, t; }" : "=r"(a) : "l"(p));
    return a;
}
__device__ __forceinline__ void cp16(uint32_t sdst, const void* gsrc) {
    asm volatile("cp.async.cg.shared.global [%0], [%1], 16;" :: "r"(sdst), "l"(gsrc) : "memory");
}
#define CP_COMMIT() asm volatile("cp.async.commit_group;" ::: "memory")
#define CP_WAIT1()  asm volatile("cp.async.wait_group 1;" ::: "memory")
#define CP_WAIT2()  asm volatile("cp.async.wait_group 2;" ::: "memory")

__device__ __forceinline__ void ldsm_x4(uint32_t (&r)[4], uint32_t addr) {
    asm volatile("ldmatrix.sync.aligned.m8n8.x4.shared.b16 {%0,%1,%2,%3}, [%4];"
                 : "=r"(r[0]), "=r"(r[1]), "=r"(r[2]), "=r"(r[3]) : "r"(addr));
}
__device__ __forceinline__ void ldsm_x4_t(uint32_t (&r)[4], uint32_t addr) {
    asm volatile("ldmatrix.sync.aligned.m8n8.x4.trans.shared.b16 {%0,%1,%2,%3}, [%4];"
                 : "=r"(r[0]), "=r"(r[1]), "=r"(r[2]), "=r"(r[3]) : "r"(addr));
}
__device__ __forceinline__ void mma16816h(float (&d)[4], const uint32_t (&a)[4],
                                          uint32_t b0, uint32_t b1) {
    asm volatile(
        "mma.sync.aligned.m16n8k16.row.col.f32.f16.f16.f32 "
        "{%0,%1,%2,%3}, {%4,%5,%6,%7}, {%8,%9}, {%0,%1,%2,%3};"
        : "+f"(d[0]), "+f"(d[1]), "+f"(d[2]), "+f"(d[3])
        : "r"(a[0]), "r"(a[1]), "r"(a[2]), "r"(a[3]), "r"(b0), "r"(b1));
}
__device__ __forceinline__ uint32_t pack_f16x2(float lo, float hi) {
    __half2 h = __float22half2_rn(make_float2(lo, hi));
    return *(uint32_t*)&h;
}

// ---------- fused fp32 -> fp16 conversions ----------
__global__ __launch_bounds__(256)
void cvt_all(const float4* __restrict__ x,  const float4* __restrict__ wq,
             const float4* __restrict__ wk, const float4* __restrict__ wv,
             const float4* __restrict__ wo,
             __half2* xh, __half2* xl,
             __half2* wqf, __half2* wkf, __half2* wvf, __half2* wof)
{
    int bid = blockIdx.x;
    if (bid < 8192) {
        size_t i = (size_t)bid * 256 + threadIdx.x;
        float4 v = x[i];
        __half hx = __float2half_rn(v.x), hy = __float2half_rn(v.y);
        __half hz = __float2half_rn(v.z), hw = __float2half_rn(v.w);
        xh[2 * i]     = __halves2half2(hx, hy);
        xh[2 * i + 1] = __halves2half2(hz, hw);
        xl[2 * i]     = __halves2half2(__float2half_rn(v.x - __half2float(hx)),
                                       __float2half_rn(v.y - __half2float(hy)));
        xl[2 * i + 1] = __halves2half2(__float2half_rn(v.z - __half2float(hz)),
                                       __float2half_rn(v.w - __half2float(hw)));
        return;
    }
    const float4* src; __half2* dst; int base;
    if      (bid < 12288) { src = wq; dst = wqf; base = bid - 8192; }
    else if (bid < 16384) { src = wk; dst = wkf; base = bid - 12288; }
    else if (bid < 20480) { src = wv; dst = wvf; base = bid - 16384; }
    else                  { src = wo; dst = wof; base = bid - 20480; }
    size_t i = (size_t)base * 256 + threadIdx.x;
    float4 v = src[i];
    dst[2 * i]     = __float22half2_rn(make_float2(v.x, v.y));
    dst[2 * i + 1] = __float22half2_rn(make_float2(v.z, v.w));
}

// =====================================================================
// fp16 HMMA GEMM: C = (Ah [+ Al]) @ B^T.  onepass_mask bit z => skip Al.
// 128x128 CTA tile, 8 warps (4m x 2n), BK=32, 64B rows + XOR swizzle.
// Group-paired pipeline, RACE-FREE: wait_group is followed by
// __syncthreads() so every warp sees every thread's completed copies.
// =====================================================================
#define BK       32
#define NKCH     (HIDDEN / BK)          // 64
#define NGRP     (NKCH / 2)             // 32
#define ROWB     64
#define TILE_B   (128 * ROWB)           // 8192
#define STAGE_B  (3 * TILE_B)           // 24576: Ah Al B
#define GEMM_SMEM (4 * STAGE_B)         // 98304

__global__ __launch_bounds__(256, 2)
void gemm2(const __half* __restrict__ Ah, const __half* __restrict__ Al,
           const __half* __restrict__ B0, const __half* __restrict__ B1,
           const __half* __restrict__ B2,
           __half* __restrict__ Ch0, __half* __restrict__ Cl0,
           __half* __restrict__ Ch1, __half* __restrict__ Cl1,
           __half* __restrict__ Cf2,
           float* __restrict__ C,
           int onepass_mask,
           int M, int N, int K)
{
    extern __shared__ __align__(128) char smem[];
    const uint32_t sbase = smem_u32(smem);
    const int tid  = threadIdx.x;
    const int wid  = tid >> 5;
    const int lane = tid & 31;
    const int wm   = wid & 3;
    const int wn   = wid >> 2;
    const int z    = blockIdx.z;
    const bool two = !((onepass_mask >> z) & 1);
    const size_t brow = (size_t)blockIdx.y * 128;
    const size_t bcol = (size_t)blockIdx.x * 128;

    const __half* Bsel = (z == 0) ? B0 : (z == 1) ? B1 : B2;

    const int row = tid >> 1;
    const int sp  = (tid & 1) * 2;
    const int wmsk = (row >> 1) & 3;
    const uint32_t soff0 = (uint32_t)(row * ROWB + ((sp    ) ^ wmsk) * 16);
    const uint32_t soff1 = (uint32_t)(row * ROWB + ((sp + 1) ^ wmsk) * 16);

    const size_t Kb = (size_t)K * 2;
    const char* pAh = (const char*)Ah   + (brow + row) * Kb + sp * 16;
    const char* pAl = (const char*)Al   + (brow + row) * Kb + sp * 16;
    const char* pB  = (const char*)Bsel + (bcol + row) * Kb + sp * 16;

#define LOAD_CHUNK(c, s) do {                                    \
        uint32_t sb_ = sbase + (uint32_t)(s) * STAGE_B;          \
        size_t g_ = (size_t)(c) * 64;                            \
        cp16(sb_ + 0 * TILE_B + soff0, pAh + g_);                \
        cp16(sb_ + 0 * TILE_B + soff1, pAh + g_ + 16);           \
        if (two) {                                               \
            cp16(sb_ + 1 * TILE_B + soff0, pAl + g_);            \
            cp16(sb_ + 1 * TILE_B + soff1, pAl + g_ + 16);       \
        }                                                        \
        cp16(sb_ + 2 * TILE_B + soff0, pB  + g_);                \
        cp16(sb_ + 2 * TILE_B + soff1, pB  + g_ + 16);           \
    } while (0)

    const int rA    = wm * 32 + (lane & 15);
    const int aSeg  = lane >> 4;
    const int maskA = (rA >> 1) & 3;
    const int rB    = wn * 64 + ((lane >> 4) << 3) + (lane & 7);
    const int bSeg  = (lane >> 3) & 1;
    const int maskB = (rB >> 1) & 3;

    float acc[2][8][4];
#pragma unroll
    for (int mt = 0; mt < 2; ++mt)
#pragma unroll
        for (int nt = 0; nt < 8; ++nt)
#pragma unroll
            for (int q = 0; q < 4; ++q) acc[mt][nt][q] = 0.f;

    LOAD_CHUNK(0, 0);
    LOAD_CHUNK(1, 1);
    CP_COMMIT();

    for (int g = 0; g < NGRP; ++g) {
        __syncthreads();                 // all warps done computing group g-1
        if (g + 1 < NGRP) {
            LOAD_CHUNK(2 * g + 2, (2 * g + 2) & 3);
            LOAD_CHUNK(2 * g + 3, (2 * g + 3) & 3);
        }
        CP_COMMIT();
        CP_WAIT1();                      // own group-g copies complete
        __syncthreads();                 // ALL threads' group-g copies visible

#pragma unroll
        for (int u = 0; u < 2; ++u) {
            const uint32_t sb = sbase + (uint32_t)((2 * g + u) & 3) * STAGE_B;

#pragma unroll
            for (int k16 = 0; k16 < 2; ++k16) {
                uint32_t ah[2][4];
#pragma unroll
                for (int mt = 0; mt < 2; ++mt) {
                    uint32_t byteoff = (uint32_t)((rA + mt * 16) * ROWB +
                                                  ((2 * k16 + aSeg) ^ maskA) * 16);
                    ldsm_x4(ah[mt], sb + 0 * TILE_B + byteoff);
                }
                uint32_t bh[4][4];
#pragma unroll
                for (int np = 0; np < 4; ++np) {
                    uint32_t byteoff = (uint32_t)((rB + np * 16) * ROWB +
                                                  ((2 * k16 + bSeg) ^ maskB) * 16);
                    ldsm_x4(bh[np], sb + 2 * TILE_B + byteoff);
                }
#pragma unroll
                for (int np = 0; np < 4; ++np)
#pragma unroll
                    for (int mt = 0; mt < 2; ++mt) {
                        mma16816h(acc[mt][2 * np + 0], ah[mt], bh[np][0], bh[np][1]);
                        mma16816h(acc[mt][2 * np + 1], ah[mt], bh[np][2], bh[np][3]);
                    }
                if (two) {
                    uint32_t al[2][4];
#pragma unroll
                    for (int mt = 0; mt < 2; ++mt) {
                        uint32_t byteoff = (uint32_t)((rA + mt * 16) * ROWB +
                                                      ((2 * k16 + aSeg) ^ maskA) * 16);
                        ldsm_x4(al[mt], sb + 1 * TILE_B + byteoff);
                    }
#pragma unroll
                    for (int np = 0; np < 4; ++np)
#pragma unroll
                        for (int mt = 0; mt < 2; ++mt) {
                            mma16816h(acc[mt][2 * np + 0], al[mt], bh[np][0], bh[np][1]);
                            mma16816h(acc[mt][2 * np + 1], al[mt], bh[np][2], bh[np][3]);
                        }
                }
            }
        }
    }

    __half* Ch = (z == 0) ? Ch0 : Ch1;
    __half* Cl = (z == 0) ? Cl0 : Cl1;
#pragma unroll
    for (int mt = 0; mt < 2; ++mt) {
        size_t r0 = brow + wm * 32 + mt * 16 + (lane >> 2);
#pragma unroll
        for (int nt = 0; nt < 8; ++nt) {
            size_t col = bcol + wn * 64 + nt * 8 + 2 * (lane & 3);
            if (C) {
                *(float2*)&C[r0 * (size_t)N + col]       = make_float2(acc[mt][nt][0], acc[mt][nt][1]);
                *(float2*)&C[(r0 + 8) * (size_t)N + col] = make_float2(acc[mt][nt][2], acc[mt][nt][3]);
            } else if (z == 2) {
#pragma unroll
                for (int hf = 0; hf < 2; ++hf) {
                    size_t idx = (r0 + 8 * hf) * (size_t)N + col;
                    *(__half2*)&Cf2[idx] = __float22half2_rn(
                        make_float2(acc[mt][nt][2 * hf], acc[mt][nt][2 * hf + 1]));
                }
            } else {
#pragma unroll
                for (int hf = 0; hf < 2; ++hf) {
                    float v0 = acc[mt][nt][2 * hf + 0];
                    float v1 = acc[mt][nt][2 * hf + 1];
                    __half h0 = __float2half_rn(v0);
                    __half h1 = __float2half_rn(v1);
                    size_t idx = (r0 + 8 * hf) * (size_t)N + col;
                    *(__half2*)&Ch[idx] = __halves2half2(h0, h1);
                    *(__half2*)&Cl[idx] = __halves2half2(
                        __float2half_rn(v0 - __half2float(h0)),
                        __float2half_rn(v1 - __half2float(h1)));
                }
            }
        }
    }
}

// =====================================================================
// FlashAttention-2 on fp16 HMMA (scores -> softmax -> PV, Q h+l preloaded,
// exp2-domain softmax). RACE-FREE: __syncthreads() after wait_group.
// =====================================================================
#define QT        128
#define SROW      272
#define AQL_OFF   34816
#define AST_OFF   69632
#define AST_SZ    52224
#define AKL_OFF   17408
#define AV_OFF    34816
#define ATTN_SMEM 226304
#define NKT       (SEQ / 64)   // 32

__global__ __launch_bounds__(256, 1)
void attn_mma(const __half* __restrict__ Qh, const __half* __restrict__ Ql,
              const __half* __restrict__ Kh, const __half* __restrict__ Kl,
              const __half* __restrict__ Vf,
              __half* __restrict__ Oh)
{
    extern __shared__ __align__(128) char smem[];
    const uint32_t sb = smem_u32(smem);
    const int tid  = threadIdx.x;
    const int wid  = tid >> 5;
    const int lane = tid & 31;
    const int b    = blockIdx.x >> 4;
    const int h    = blockIdx.x & 15;
    const int qt   = blockIdx.y;

    // scale2 = (1/sqrt(128)) * log2(e)
    const float scale2 = 0.12751969f;
    const size_t hoff  = (size_t)h * HDIM;
    const size_t qrow0 = (size_t)b * SEQ + (size_t)qt * QT;
    const size_t krow0 = (size_t)b * SEQ;

#pragma unroll
    for (int it = 0; it < 8; ++it) {
        int idx = it * 256 + tid;
        int r   = idx >> 4;
        int ch  = idx & 15;
        size_t g = ((qrow0 + r) * HIDDEN + hoff + ch * 8) * 2;
        uint32_t d = sb + (uint32_t)(r * SROW + ch * 16);
        cp16(d,           (const char*)Qh + g);
        cp16(d + AQL_OFF, (const char*)Ql + g);
    }
#define LOAD_KV(c, s) do {                                                     \
        uint32_t st_ = sb + AST_OFF + (uint32_t)(s) * AST_SZ;                  \
        _Pragma("unroll")                                                      \
        for (int it_ = 0; it_ < 4; ++it_) {                                    \
            int idx_ = it_ * 256 + tid;                                        \
            int r_  = idx_ >> 4;                                               \
            int ch_ = idx_ & 15;                                               \
            size_t g_ = ((krow0 + (size_t)(c) * 64 + r_) * HIDDEN + hoff + ch_ * 8) * 2; \
            uint32_t d_ = st_ + (uint32_t)(r_ * SROW + ch_ * 16);              \
            cp16(d_,           (const char*)Kh + g_);                          \
            cp16(d_ + AKL_OFF, (const char*)Kl + g_);                          \
            cp16(d_ + AV_OFF,  (const char*)Vf + g_);                          \
        }                                                                      \
    } while (0)

    LOAD_KV(0, 0); CP_COMMIT();
    LOAD_KV(1, 1); CP_COMMIT();
    CP_WAIT1();
    __syncthreads();              // Q + KV0 visible to all threads

    // ---- preload Q hi AND lo A-frags (Q invariant over kv tiles) ----
    const int arow = lane & 15;
    const int aseg = lane >> 4;
    const uint32_t qbase  = sb + (uint32_t)((wid * 16 + arow) * SROW + aseg * 16);
    const uint32_t qlbase = qbase + AQL_OFF;
    uint32_t qh[8][4], ql[8][4];
#pragma unroll
    for (int ks = 0; ks < 8; ++ks) {
        ldsm_x4(qh[ks], qbase  + ks * 32);
        ldsm_x4(ql[ks], qlbase + ks * 32);
    }

    float Oacc[16][4];
#pragma unroll
    for (int nt = 0; nt < 16; ++nt)
#pragma unroll
        for (int q = 0; q < 4; ++q) Oacc[nt][q] = 0.f;
    float m0 = -1e30f, m1 = -1e30f, l0 = 0.f, l1 = 0.f;

    const int brow = ((lane >> 4) << 3) + (lane & 7);
    const int bseg = (lane >> 3) & 1;

    int stage = 0;
    for (int kt = 0; kt < NKT; ++kt) {
        __syncthreads();          // all warps done with tile kt-1
        if (kt + 2 < NKT) {
            int s2 = stage + 2; if (s2 >= 3) s2 -= 3;
            LOAD_KV(kt + 2, s2);
        }
        CP_COMMIT();
        CP_WAIT2();               // own tile-kt copies complete
        __syncthreads();          // ALL threads' tile-kt copies visible

        const uint32_t st = sb + AST_OFF + (uint32_t)stage * AST_SZ;

        float S[8][4];
#pragma unroll
        for (int nt = 0; nt < 8; ++nt)
#pragma unroll
            for (int q = 0; q < 4; ++q) S[nt][q] = 0.f;

#pragma unroll
        for (int ks = 0; ks < 8; ++ks) {
            uint32_t koff = (uint32_t)(brow * SROW + ks * 32 + bseg * 16);
            uint32_t kh4[4][4];
#pragma unroll
            for (int p = 0; p < 4; ++p) ldsm_x4(kh4[p], st + p * (16 * SROW) + koff);
#pragma unroll
            for (int p = 0; p < 4; ++p) {
                mma16816h(S[2 * p + 0], qh[ks], kh4[p][0], kh4[p][1]);
                mma16816h(S[2 * p + 1], qh[ks], kh4[p][2], kh4[p][3]);
            }
#pragma unroll
            for (int p = 0; p < 4; ++p) {
                mma16816h(S[2 * p + 0], ql[ks], kh4[p][0], kh4[p][1]);
                mma16816h(S[2 * p + 1], ql[ks], kh4[p][2], kh4[p][3]);
            }
#pragma unroll
            for (int p = 0; p < 4; ++p) {
                uint32_t kl4[4];
                ldsm_x4(kl4, st + AKL_OFF + p * (16 * SROW) + koff);
                mma16816h(S[2 * p + 0], qh[ks], kl4[0], kl4[1]);
                mma16816h(S[2 * p + 1], qh[ks], kl4[2], kl4[3]);
            }
        }

        // ---- online softmax (exp2 domain) ----
        float mx0 = -1e30f, mx1 = -1e30f;
#pragma unroll
        for (int nt = 0; nt < 8; ++nt) {
            mx0 = fmaxf(mx0, fmaxf(S[nt][0], S[nt][1]));
            mx1 = fmaxf(mx1, fmaxf(S[nt][2], S[nt][3]));
        }
        mx0 = fmaxf(mx0, __shfl_xor_sync(0xffffffffu, mx0, 1));
        mx0 = fmaxf(mx0, __shfl_xor_sync(0xffffffffu, mx0, 2));
        mx1 = fmaxf(mx1, __shfl_xor_sync(0xffffffffu, mx1, 1));
        mx1 = fmaxf(mx1, __shfl_xor_sync(0xffffffffu, mx1, 2));
        float mn0 = fmaxf(m0, mx0), mn1 = fmaxf(m1, mx1);
        float cf0 = exp2f(scale2 * (m0 - mn0));
        float cf1 = exp2f(scale2 * (m1 - mn1));
        m0 = mn0; m1 = mn1;
        float bb0 = -scale2 * mn0, bb1 = -scale2 * mn1;
        float rs0 = 0.f, rs1 = 0.f;
#pragma unroll
        for (int nt = 0; nt < 8; ++nt) {
            S[nt][0] = exp2f(fmaf(S[nt][0], scale2, bb0));
            S[nt][1] = exp2f(fmaf(S[nt][1], scale2, bb0));
            S[nt][2] = exp2f(fmaf(S[nt][2], scale2, bb1));
            S[nt][3] = exp2f(fmaf(S[nt][3], scale2, bb1));
            rs0 += S[nt][0] + S[nt][1];
            rs1 += S[nt][2] + S[nt][3];
        }
        rs0 += __shfl_xor_sync(0xffffffffu, rs0, 1);
        rs0 += __shfl_xor_sync(0xffffffffu, rs0, 2);
        rs1 += __shfl_xor_sync(0xffffffffu, rs1, 1);
        rs1 += __shfl_xor_sync(0xffffffffu, rs1, 2);
        l0 = l0 * cf0 + rs0;
        l1 = l1 * cf1 + rs1;

#pragma unroll
        for (int nt = 0; nt < 16; ++nt) {
            Oacc[nt][0] *= cf0; Oacc[nt][1] *= cf0;
            Oacc[nt][2] *= cf1; Oacc[nt][3] *= cf1;
        }
        uint32_t pa[4][4];
#pragma unroll
        for (int t = 0; t < 4; ++t) {
            pa[t][0] = pack_f16x2(S[2 * t][0],     S[2 * t][1]);
            pa[t][1] = pack_f16x2(S[2 * t][2],     S[2 * t][3]);
            pa[t][2] = pack_f16x2(S[2 * t + 1][0], S[2 * t + 1][1]);
            pa[t][3] = pack_f16x2(S[2 * t + 1][2], S[2 * t + 1][3]);
        }

        // ---- PV (fp16 x fp16 -> fp32) ----
        const uint32_t vbase = st + AV_OFF;
#pragma unroll
        for (int t = 0; t < 4; ++t) {
            uint32_t rowoff = vbase + (uint32_t)((t * 16 + (lane & 15)) * SROW + (lane >> 4) * 16);
#pragma unroll
            for (int dp = 0; dp < 8; ++dp) {
                uint32_t vb[4];
                ldsm_x4_t(vb, rowoff + dp * 32);
                mma16816h(Oacc[2 * dp + 0], pa[t], vb[0], vb[1]);
                mma16816h(Oacc[2 * dp + 1], pa[t], vb[2], vb[3]);
            }
        }
        stage = (stage == 2) ? 0 : stage + 1;
    }

    // ---- epilogue: normalize, write single fp16 O ----
    float inv0 = 1.0f / l0, inv1 = 1.0f / l1;
    int r = wid * 16 + (lane >> 2);
    size_t g0 = (qrow0 + r) * HIDDEN + hoff;
    size_t g1 = g0 + 8 * HIDDEN;
#pragma unroll
    for (int nt = 0; nt < 16; ++nt) {
        int col = nt * 8 + 2 * (lane & 3);
        *(__half2*)&Oh[g0 + col] = __float22half2_rn(
            make_float2(Oacc[nt][0] * inv0, Oacc[nt][1] * inv0));
        *(__half2*)&Oh[g1 + col] = __float22half2_rn(
            make_float2(Oacc[nt][2] * inv1, Oacc[nt][3] * inv1));
    }
}

// =====================================================================
extern "C" void kernel_launch(void* const* d_in, const int* in_sizes, int n_in,
                              void* d_out, int out_size)
{
    const float* x  = (const float*)d_in[0];
    const float* wq = (const float*)d_in[1];
    const float* wk = (const float*)d_in[2];
    const float* wv = (const float*)d_in[3];
    const float* wo = (const float*)d_in[4];
    float* out = (float*)d_out;

    __half *xh, *xl, *oh, *qbh, *qbl, *kbh, *kbl, *vf;
    __half *wqf, *wkf, *wvf, *wof;
    cudaGetSymbolAddress((void**)&xh, g_xh);   cudaGetSymbolAddress((void**)&xl, g_xl);
    cudaGetSymbolAddress((void**)&oh, g_oh);
    cudaGetSymbolAddress((void**)&qbh, g_qbh); cudaGetSymbolAddress((void**)&qbl, g_qbl);
    cudaGetSymbolAddress((void**)&kbh, g_kbh); cudaGetSymbolAddress((void**)&kbl, g_kbl);
    cudaGetSymbolAddress((void**)&vf, g_vf);
    cudaGetSymbolAddress((void**)&wqf, g_wqf); cudaGetSymbolAddress((void**)&wkf, g_wkf);
    cudaGetSymbolAddress((void**)&wvf, g_wvf); cudaGetSymbolAddress((void**)&wof, g_wof);

    const int M = MROWS;   // 4096

    cvt_all<<<24576, 256>>>((const float4*)x, (const float4*)wq, (const float4*)wk,
                            (const float4*)wv, (const float4*)wo,
                            (__half2*)xh, (__half2*)xl,
                            (__half2*)wqf, (__half2*)wkf, (__half2*)wvf, (__half2*)wof);

    cudaFuncSetAttribute(gemm2, cudaFuncAttributeMaxDynamicSharedMemorySize, GEMM_SMEM);
    // fused QKV: z=0 -> Q (2-pass, h/l out), z=1 -> K (2-pass, h/l out),
    //            z=2 -> V (1-pass, single fp16 out)
    gemm2<<<dim3(HIDDEN / 128, M / 128, 3), 256, GEMM_SMEM>>>(
        xh, xl, wqf, wkf, wvf, qbh, qbl, kbh, kbl, vf, nullptr,
        /*onepass_mask=*/0b100, M, HIDDEN, HIDDEN);

    cudaFuncSetAttribute(attn_mma, cudaFuncAttributeMaxDynamicSharedMemorySize, ATTN_SMEM);
    attn_mma<<<dim3(BATCH * NHEADS, SEQ / QT), 256, ATTN_SMEM>>>(qbh, qbl, kbh, kbl, vf, oh);

    // output projection: 1-pass (O single fp16), fp32 out
    gemm2<<<dim3(HIDDEN / 128, M / 128, 1), 256, GEMM_SMEM>>>(
        oh, oh, wof, wof, wof, nullptr, nullptr, nullptr, nullptr, nullptr, out,
        /*onepass_mask=*/0b001, M, HIDDEN, HIDDEN);
}

// round 17
// speedup vs baseline: 1.3308x; 1.0901x over previous
#include <cuda_runtime.h>
#include <cuda_fp16.h>
#include <cstdint>

#define HIDDEN 2048
#define SEQ    2048
#define BATCH  2
#define NHEADS 16
#define HDIM   128
#define MROWS  (BATCH * SEQ)   // 4096

// ---------- scratch (all fp16) ----------
__device__ __half g_xh[MROWS * HIDDEN], g_xl[MROWS * HIDDEN];
__device__ __half g_oh[MROWS * HIDDEN];
__device__ __half g_qbh[MROWS * HIDDEN], g_qbl[MROWS * HIDDEN];
__device__ __half g_kf[MROWS * HIDDEN];
__device__ __half g_vf[MROWS * HIDDEN];
__device__ __half g_wqf[HIDDEN * HIDDEN], g_wkf[HIDDEN * HIDDEN];
__device__ __half g_wvf[HIDDEN * HIDDEN], g_wof[HIDDEN * HIDDEN];

// ---------- PTX wrappers (sm_80/90-era, valid on compute_103) ----------
__device__ __forceinline__ uint32_t smem_u32(const void* p) {
    uint32_t a;
    asm("{ .reg .u64 t; cvta.to.shared.u64 t, %1; cvt.u32.u64 %0, t; }" : "=r"(a) : "l"(p));
    return a;
}
__device__ __forceinline__ void cp16(uint32_t sdst, const void* gsrc) {
    asm volatile("cp.async.cg.shared.global [%0], [%1], 16;" :: "r"(sdst), "l"(gsrc) : "memory");
}
#define CP_COMMIT() asm volatile("cp.async.commit_group;" ::: "memory")
#define CP_WAIT1()  asm volatile("cp.async.wait_group 1;" ::: "memory")
#define CP_WAIT2()  asm volatile("cp.async.wait_group 2;" ::: "memory")

__device__ __forceinline__ void ldsm_x4(uint32_t (&r)[4], uint32_t addr) {
    asm volatile("ldmatrix.sync.aligned.m8n8.x4.shared.b16 {%0,%1,%2,%3}, [%4];"
                 : "=r"(r[0]), "=r"(r[1]), "=r"(r[2]), "=r"(r[3]) : "r"(addr));
}
__device__ __forceinline__ void ldsm_x4_t(uint32_t (&r)[4], uint32_t addr) {
    asm volatile("ldmatrix.sync.aligned.m8n8.x4.trans.shared.b16 {%0,%1,%2,%3}, [%4];"
                 : "=r"(r[0]), "=r"(r[1]), "=r"(r[2]), "=r"(r[3]) : "r"(addr));
}
__device__ __forceinline__ void mma16816h(float (&d)[4], const uint32_t (&a)[4],
                                          uint32_t b0, uint32_t b1) {
    asm volatile(
        "mma.sync.aligned.m16n8k16.row.col.f32.f16.f16.f32 "
        "{%0,%1,%2,%3}, {%4,%5,%6,%7}, {%8,%9}, {%0,%1,%2,%3};"
        : "+f"(d[0]), "+f"(d[1]), "+f"(d[2]), "+f"(d[3])
        : "r"(a[0]), "r"(a[1]), "r"(a[2]), "r"(a[3]), "r"(b0), "r"(b1));
}
__device__ __forceinline__ uint32_t pack_f16x2(float lo, float hi) {
    __half2 h = __float22half2_rn(make_float2(lo, hi));
    return *(uint32_t*)&h;
}

// ---------- fused fp32 -> fp16 conversions ----------
__global__ __launch_bounds__(256)
void cvt_all(const float4* __restrict__ x,  const float4* __restrict__ wq,
             const float4* __restrict__ wk, const float4* __restrict__ wv,
             const float4* __restrict__ wo,
             __half2* xh, __half2* xl,
             __half2* wqf, __half2* wkf, __half2* wvf, __half2* wof)
{
    int bid = blockIdx.x;
    if (bid < 8192) {
        size_t i = (size_t)bid * 256 + threadIdx.x;
        float4 v = x[i];
        __half hx = __float2half_rn(v.x), hy = __float2half_rn(v.y);
        __half hz = __float2half_rn(v.z), hw = __float2half_rn(v.w);
        xh[2 * i]     = __halves2half2(hx, hy);
        xh[2 * i + 1] = __halves2half2(hz, hw);
        xl[2 * i]     = __halves2half2(__float2half_rn(v.x - __half2float(hx)),
                                       __float2half_rn(v.y - __half2float(hy)));
        xl[2 * i + 1] = __halves2half2(__float2half_rn(v.z - __half2float(hz)),
                                       __float2half_rn(v.w - __half2float(hw)));
        return;
    }
    const float4* src; __half2* dst; int base;
    if      (bid < 12288) { src = wq; dst = wqf; base = bid - 8192; }
    else if (bid < 16384) { src = wk; dst = wkf; base = bid - 12288; }
    else if (bid < 20480) { src = wv; dst = wvf; base = bid - 16384; }
    else                  { src = wo; dst = wof; base = bid - 20480; }
    size_t i = (size_t)base * 256 + threadIdx.x;
    float4 v = src[i];
    dst[2 * i]     = __float22half2_rn(make_float2(v.x, v.y));
    dst[2 * i + 1] = __float22half2_rn(make_float2(v.z, v.w));
}

// =====================================================================
// fp16 HMMA GEMM: C = (Ah [+ Al]) @ B^T.  onepass_mask bit z => skip Al.
// 128x128 CTA tile, 8 warps (4m x 2n), BK=32, 64B rows + XOR swizzle.
// Group-paired pipeline, race-free (sync after wait_group).
// Outputs: z=0 -> fp16 hi/lo (Ch0,Cl0); z=1 -> fp16 Cf1; z=2 -> fp16 Cf2;
//          C != null -> fp32 (overrides).
// =====================================================================
#define BK       32
#define NKCH     (HIDDEN / BK)          // 64
#define NGRP     (NKCH / 2)             // 32
#define ROWB     64
#define TILE_B   (128 * ROWB)           // 8192
#define STAGE_B  (3 * TILE_B)           // 24576: Ah Al B
#define GEMM_SMEM (4 * STAGE_B)         // 98304

__global__ __launch_bounds__(256, 2)
void gemm2(const __half* __restrict__ Ah, const __half* __restrict__ Al,
           const __half* __restrict__ B0, const __half* __restrict__ B1,
           const __half* __restrict__ B2,
           __half* __restrict__ Ch0, __half* __restrict__ Cl0,
           __half* __restrict__ Cf1, __half* __restrict__ Cf2,
           float* __restrict__ C,
           int onepass_mask,
           int M, int N, int K)
{
    extern __shared__ __align__(128) char smem[];
    const uint32_t sbase = smem_u32(smem);
    const int tid  = threadIdx.x;
    const int wid  = tid >> 5;
    const int lane = tid & 31;
    const int wm   = wid & 3;
    const int wn   = wid >> 2;
    const int z    = blockIdx.z;
    const bool two = !((onepass_mask >> z) & 1);
    const size_t brow = (size_t)blockIdx.y * 128;
    const size_t bcol = (size_t)blockIdx.x * 128;

    const __half* Bsel = (z == 0) ? B0 : (z == 1) ? B1 : B2;

    const int row = tid >> 1;
    const int sp  = (tid & 1) * 2;
    const int wmsk = (row >> 1) & 3;
    const uint32_t soff0 = (uint32_t)(row * ROWB + ((sp    ) ^ wmsk) * 16);
    const uint32_t soff1 = (uint32_t)(row * ROWB + ((sp + 1) ^ wmsk) * 16);

    const size_t Kb = (size_t)K * 2;
    const char* pAh = (const char*)Ah   + (brow + row) * Kb + sp * 16;
    const char* pAl = (const char*)Al   + (brow + row) * Kb + sp * 16;
    const char* pB  = (const char*)Bsel + (bcol + row) * Kb + sp * 16;

#define LOAD_CHUNK(c, s) do {                                    \
        uint32_t sb_ = sbase + (uint32_t)(s) * STAGE_B;          \
        size_t g_ = (size_t)(c) * 64;                            \
        cp16(sb_ + 0 * TILE_B + soff0, pAh + g_);                \
        cp16(sb_ + 0 * TILE_B + soff1, pAh + g_ + 16);           \
        if (two) {                                               \
            cp16(sb_ + 1 * TILE_B + soff0, pAl + g_);            \
            cp16(sb_ + 1 * TILE_B + soff1, pAl + g_ + 16);       \
        }                                                        \
        cp16(sb_ + 2 * TILE_B + soff0, pB  + g_);                \
        cp16(sb_ + 2 * TILE_B + soff1, pB  + g_ + 16);           \
    } while (0)

    const int rA    = wm * 32 + (lane & 15);
    const int aSeg  = lane >> 4;
    const int maskA = (rA >> 1) & 3;
    const int rB    = wn * 64 + ((lane >> 4) << 3) + (lane & 7);
    const int bSeg  = (lane >> 3) & 1;
    const int maskB = (rB >> 1) & 3;

    float acc[2][8][4];
#pragma unroll
    for (int mt = 0; mt < 2; ++mt)
#pragma unroll
        for (int nt = 0; nt < 8; ++nt)
#pragma unroll
            for (int q = 0; q < 4; ++q) acc[mt][nt][q] = 0.f;

    LOAD_CHUNK(0, 0);
    LOAD_CHUNK(1, 1);
    CP_COMMIT();

    for (int g = 0; g < NGRP; ++g) {
        __syncthreads();                 // all warps done computing group g-1
        if (g + 1 < NGRP) {
            LOAD_CHUNK(2 * g + 2, (2 * g + 2) & 3);
            LOAD_CHUNK(2 * g + 3, (2 * g + 3) & 3);
        }
        CP_COMMIT();
        CP_WAIT1();                      // own group-g copies complete
        __syncthreads();                 // ALL threads' group-g copies visible

#pragma unroll
        for (int u = 0; u < 2; ++u) {
            const uint32_t sb = sbase + (uint32_t)((2 * g + u) & 3) * STAGE_B;

#pragma unroll
            for (int k16 = 0; k16 < 2; ++k16) {
                uint32_t ah[2][4];
#pragma unroll
                for (int mt = 0; mt < 2; ++mt) {
                    uint32_t byteoff = (uint32_t)((rA + mt * 16) * ROWB +
                                                  ((2 * k16 + aSeg) ^ maskA) * 16);
                    ldsm_x4(ah[mt], sb + 0 * TILE_B + byteoff);
                }
                uint32_t bh[4][4];
#pragma unroll
                for (int np = 0; np < 4; ++np) {
                    uint32_t byteoff = (uint32_t)((rB + np * 16) * ROWB +
                                                  ((2 * k16 + bSeg) ^ maskB) * 16);
                    ldsm_x4(bh[np], sb + 2 * TILE_B + byteoff);
                }
#pragma unroll
                for (int np = 0; np < 4; ++np)
#pragma unroll
                    for (int mt = 0; mt < 2; ++mt) {
                        mma16816h(acc[mt][2 * np + 0], ah[mt], bh[np][0], bh[np][1]);
                        mma16816h(acc[mt][2 * np + 1], ah[mt], bh[np][2], bh[np][3]);
                    }
                if (two) {
                    uint32_t al[2][4];
#pragma unroll
                    for (int mt = 0; mt < 2; ++mt) {
                        uint32_t byteoff = (uint32_t)((rA + mt * 16) * ROWB +
                                                      ((2 * k16 + aSeg) ^ maskA) * 16);
                        ldsm_x4(al[mt], sb + 1 * TILE_B + byteoff);
                    }
#pragma unroll
                    for (int np = 0; np < 4; ++np)
#pragma unroll
                        for (int mt = 0; mt < 2; ++mt) {
                            mma16816h(acc[mt][2 * np + 0], al[mt], bh[np][0], bh[np][1]);
                            mma16816h(acc[mt][2 * np + 1], al[mt], bh[np][2], bh[np][3]);
                        }
                }
            }
        }
    }

#pragma unroll
    for (int mt = 0; mt < 2; ++mt) {
        size_t r0 = brow + wm * 32 + mt * 16 + (lane >> 2);
#pragma unroll
        for (int nt = 0; nt < 8; ++nt) {
            size_t col = bcol + wn * 64 + nt * 8 + 2 * (lane & 3);
            if (C) {
                *(float2*)&C[r0 * (size_t)N + col]       = make_float2(acc[mt][nt][0], acc[mt][nt][1]);
                *(float2*)&C[(r0 + 8) * (size_t)N + col] = make_float2(acc[mt][nt][2], acc[mt][nt][3]);
            } else if (z == 0) {
#pragma unroll
                for (int hf = 0; hf < 2; ++hf) {
                    float v0 = acc[mt][nt][2 * hf + 0];
                    float v1 = acc[mt][nt][2 * hf + 1];
                    __half h0 = __float2half_rn(v0);
                    __half h1 = __float2half_rn(v1);
                    size_t idx = (r0 + 8 * hf) * (size_t)N + col;
                    *(__half2*)&Ch0[idx] = __halves2half2(h0, h1);
                    *(__half2*)&Cl0[idx] = __halves2half2(
                        __float2half_rn(v0 - __half2float(h0)),
                        __float2half_rn(v1 - __half2float(h1)));
                }
            } else {
                __half* Cf = (z == 1) ? Cf1 : Cf2;
#pragma unroll
                for (int hf = 0; hf < 2; ++hf) {
                    size_t idx = (r0 + 8 * hf) * (size_t)N + col;
                    *(__half2*)&Cf[idx] = __float22half2_rn(
                        make_float2(acc[mt][nt][2 * hf], acc[mt][nt][2 * hf + 1]));
                }
            }
        }
    }
}

// =====================================================================
// FlashAttention-2 on fp16 HMMA. Scores: 2-pass (Qh*K + Ql*K), K single fp16.
// PV: fp16 P and V. Race-free pipeline (sync after wait_group).
// smem: Qh @0 | Ql @34816 | stage s @69632+s*34816: K | V(+17408)
// total 174080 bytes.
// =====================================================================
#define QT        128
#define SROW      272
#define AQL_OFF   34816
#define AST_OFF   69632
#define AST_SZ    34816
#define AV_OFF    17408
#define ATTN_SMEM 174080
#define NKT       (SEQ / 64)   // 32

__global__ __launch_bounds__(256, 1)
void attn_mma(const __half* __restrict__ Qh, const __half* __restrict__ Ql,
              const __half* __restrict__ Kf, const __half* __restrict__ Vf,
              __half* __restrict__ Oh)
{
    extern __shared__ __align__(128) char smem[];
    const uint32_t sb = smem_u32(smem);
    const int tid  = threadIdx.x;
    const int wid  = tid >> 5;
    const int lane = tid & 31;
    const int b    = blockIdx.x >> 4;
    const int h    = blockIdx.x & 15;
    const int qt   = blockIdx.y;

    // scale2 = (1/sqrt(128)) * log2(e)
    const float scale2 = 0.12751969f;
    const size_t hoff  = (size_t)h * HDIM;
    const size_t qrow0 = (size_t)b * SEQ + (size_t)qt * QT;
    const size_t krow0 = (size_t)b * SEQ;

#pragma unroll
    for (int it = 0; it < 8; ++it) {
        int idx = it * 256 + tid;
        int r   = idx >> 4;
        int ch  = idx & 15;
        size_t g = ((qrow0 + r) * HIDDEN + hoff + ch * 8) * 2;
        uint32_t d = sb + (uint32_t)(r * SROW + ch * 16);
        cp16(d,           (const char*)Qh + g);
        cp16(d + AQL_OFF, (const char*)Ql + g);
    }
#define LOAD_KV(c, s) do {                                                     \
        uint32_t st_ = sb + AST_OFF + (uint32_t)(s) * AST_SZ;                  \
        _Pragma("unroll")                                                      \
        for (int it_ = 0; it_ < 4; ++it_) {                                    \
            int idx_ = it_ * 256 + tid;                                        \
            int r_  = idx_ >> 4;                                               \
            int ch_ = idx_ & 15;                                               \
            size_t g_ = ((krow0 + (size_t)(c) * 64 + r_) * HIDDEN + hoff + ch_ * 8) * 2; \
            uint32_t d_ = st_ + (uint32_t)(r_ * SROW + ch_ * 16);              \
            cp16(d_,          (const char*)Kf + g_);                           \
            cp16(d_ + AV_OFF, (const char*)Vf + g_);                           \
        }                                                                      \
    } while (0)

    LOAD_KV(0, 0); CP_COMMIT();
    LOAD_KV(1, 1); CP_COMMIT();
    CP_WAIT1();
    __syncthreads();              // Q + KV0 visible to all threads

    // ---- preload Q hi AND lo A-frags (Q invariant over kv tiles) ----
    const int arow = lane & 15;
    const int aseg = lane >> 4;
    const uint32_t qbase  = sb + (uint32_t)((wid * 16 + arow) * SROW + aseg * 16);
    const uint32_t qlbase = qbase + AQL_OFF;
    uint32_t qh[8][4], ql[8][4];
#pragma unroll
    for (int ks = 0; ks < 8; ++ks) {
        ldsm_x4(qh[ks], qbase  + ks * 32);
        ldsm_x4(ql[ks], qlbase + ks * 32);
    }

    float Oacc[16][4];
#pragma unroll
    for (int nt = 0; nt < 16; ++nt)
#pragma unroll
        for (int q = 0; q < 4; ++q) Oacc[nt][q] = 0.f;
    float m0 = -1e30f, m1 = -1e30f, l0 = 0.f, l1 = 0.f;

    const int brow = ((lane >> 4) << 3) + (lane & 7);
    const int bseg = (lane >> 3) & 1;

    int stage = 0;
    for (int kt = 0; kt < NKT; ++kt) {
        __syncthreads();          // all warps done with tile kt-1
        if (kt + 2 < NKT) {
            int s2 = stage + 2; if (s2 >= 3) s2 -= 3;
            LOAD_KV(kt + 2, s2);
        }
        CP_COMMIT();
        CP_WAIT2();               // own tile-kt copies complete
        __syncthreads();          // ALL threads' tile-kt copies visible

        const uint32_t st = sb + AST_OFF + (uint32_t)stage * AST_SZ;

        float S[8][4];
#pragma unroll
        for (int nt = 0; nt < 8; ++nt)
#pragma unroll
            for (int q = 0; q < 4; ++q) S[nt][q] = 0.f;

        // ---- scores: 2 passes (Qh*K, Ql*K), K single fp16 ----
#pragma unroll
        for (int ks = 0; ks < 8; ++ks) {
            uint32_t koff = (uint32_t)(brow * SROW + ks * 32 + bseg * 16);
            uint32_t kh4[4][4];
#pragma unroll
            for (int p = 0; p < 4; ++p) ldsm_x4(kh4[p], st + p * (16 * SROW) + koff);
#pragma unroll
            for (int p = 0; p < 4; ++p) {
                mma16816h(S[2 * p + 0], qh[ks], kh4[p][0], kh4[p][1]);
                mma16816h(S[2 * p + 1], qh[ks], kh4[p][2], kh4[p][3]);
            }
#pragma unroll
            for (int p = 0; p < 4; ++p) {
                mma16816h(S[2 * p + 0], ql[ks], kh4[p][0], kh4[p][1]);
                mma16816h(S[2 * p + 1], ql[ks], kh4[p][2], kh4[p][3]);
            }
        }

        // ---- online softmax (exp2 domain) ----
        float mx0 = -1e30f, mx1 = -1e30f;
#pragma unroll
        for (int nt = 0; nt < 8; ++nt) {
            mx0 = fmaxf(mx0, fmaxf(S[nt][0], S[nt][1]));
            mx1 = fmaxf(mx1, fmaxf(S[nt][2], S[nt][3]));
        }
        mx0 = fmaxf(mx0, __shfl_xor_sync(0xffffffffu, mx0, 1));
        mx0 = fmaxf(mx0, __shfl_xor_sync(0xffffffffu, mx0, 2));
        mx1 = fmaxf(mx1, __shfl_xor_sync(0xffffffffu, mx1, 1));
        mx1 = fmaxf(mx1, __shfl_xor_sync(0xffffffffu, mx1, 2));
        float mn0 = fmaxf(m0, mx0), mn1 = fmaxf(m1, mx1);
        float cf0 = exp2f(scale2 * (m0 - mn0));
        float cf1 = exp2f(scale2 * (m1 - mn1));
        m0 = mn0; m1 = mn1;
        float bb0 = -scale2 * mn0, bb1 = -scale2 * mn1;
        float rs0 = 0.f, rs1 = 0.f;
#pragma unroll
        for (int nt = 0; nt < 8; ++nt) {
            S[nt][0] = exp2f(fmaf(S[nt][0], scale2, bb0));
            S[nt][1] = exp2f(fmaf(S[nt][1], scale2, bb0));
            S[nt][2] = exp2f(fmaf(S[nt][2], scale2, bb1));
            S[nt][3] = exp2f(fmaf(S[nt][3], scale2, bb1));
            rs0 += S[nt][0] + S[nt][1];
            rs1 += S[nt][2] + S[nt][3];
        }
        rs0 += __shfl_xor_sync(0xffffffffu, rs0, 1);
        rs0 += __shfl_xor_sync(0xffffffffu, rs0, 2);
        rs1 += __shfl_xor_sync(0xffffffffu, rs1, 1);
        rs1 += __shfl_xor_sync(0xffffffffu, rs1, 2);
        l0 = l0 * cf0 + rs0;
        l1 = l1 * cf1 + rs1;

#pragma unroll
        for (int nt = 0; nt < 16; ++nt) {
            Oacc[nt][0] *= cf0; Oacc[nt][1] *= cf0;
            Oacc[nt][2] *= cf1; Oacc[nt][3] *= cf1;
        }
        uint32_t pa[4][4];
#pragma unroll
        for (int t = 0; t < 4; ++t) {
            pa[t][0] = pack_f16x2(S[2 * t][0],     S[2 * t][1]);
            pa[t][1] = pack_f16x2(S[2 * t][2],     S[2 * t][3]);
            pa[t][2] = pack_f16x2(S[2 * t + 1][0], S[2 * t + 1][1]);
            pa[t][3] = pack_f16x2(S[2 * t + 1][2], S[2 * t + 1][3]);
        }

        // ---- PV (fp16 x fp16 -> fp32) ----
        const uint32_t vbase = st + AV_OFF;
#pragma unroll
        for (int t = 0; t < 4; ++t) {
            uint32_t rowoff = vbase + (uint32_t)((t * 16 + (lane & 15)) * SROW + (lane >> 4) * 16);
#pragma unroll
            for (int dp = 0; dp < 8; ++dp) {
                uint32_t vb[4];
                ldsm_x4_t(vb, rowoff + dp * 32);
                mma16816h(Oacc[2 * dp + 0], pa[t], vb[0], vb[1]);
                mma16816h(Oacc[2 * dp + 1], pa[t], vb[2], vb[3]);
            }
        }
        stage = (stage == 2) ? 0 : stage + 1;
    }

    // ---- epilogue: normalize, write single fp16 O ----
    float inv0 = 1.0f / l0, inv1 = 1.0f / l1;
    int r = wid * 16 + (lane >> 2);
    size_t g0 = (qrow0 + r) * HIDDEN + hoff;
    size_t g1 = g0 + 8 * HIDDEN;
#pragma unroll
    for (int nt = 0; nt < 16; ++nt) {
        int col = nt * 8 + 2 * (lane & 3);
        *(__half2*)&Oh[g0 + col] = __float22half2_rn(
            make_float2(Oacc[nt][0] * inv0, Oacc[nt][1] * inv0));
        *(__half2*)&Oh[g1 + col] = __float22half2_rn(
            make_float2(Oacc[nt][2] * inv1, Oacc[nt][3] * inv1));
    }
}

// =====================================================================
extern "C" void kernel_launch(void* const* d_in, const int* in_sizes, int n_in,
                              void* d_out, int out_size)
{
    const float* x  = (const float*)d_in[0];
    const float* wq = (const float*)d_in[1];
    const float* wk = (const float*)d_in[2];
    const float* wv = (const float*)d_in[3];
    const float* wo = (const float*)d_in[4];
    float* out = (float*)d_out;

    __half *xh, *xl, *oh, *qbh, *qbl, *kf, *vf;
    __half *wqf, *wkf, *wvf, *wof;
    cudaGetSymbolAddress((void**)&xh, g_xh);   cudaGetSymbolAddress((void**)&xl, g_xl);
    cudaGetSymbolAddress((void**)&oh, g_oh);
    cudaGetSymbolAddress((void**)&qbh, g_qbh); cudaGetSymbolAddress((void**)&qbl, g_qbl);
    cudaGetSymbolAddress((void**)&kf, g_kf);
    cudaGetSymbolAddress((void**)&vf, g_vf);
    cudaGetSymbolAddress((void**)&wqf, g_wqf); cudaGetSymbolAddress((void**)&wkf, g_wkf);
    cudaGetSymbolAddress((void**)&wvf, g_wvf); cudaGetSymbolAddress((void**)&wof, g_wof);

    const int M = MROWS;   // 4096

    cvt_all<<<24576, 256>>>((const float4*)x, (const float4*)wq, (const float4*)wk,
                            (const float4*)wv, (const float4*)wo,
                            (__half2*)xh, (__half2*)xl,
                            (__half2*)wqf, (__half2*)wkf, (__half2*)wvf, (__half2*)wof);

    cudaFuncSetAttribute(gemm2, cudaFuncAttributeMaxDynamicSharedMemorySize, GEMM_SMEM);
    // fused QKV: z=0 -> Q (2-pass, hi/lo out), z=1 -> K (2-pass, single fp16 out),
    //            z=2 -> V (1-pass, single fp16 out)
    gemm2<<<dim3(HIDDEN / 128, M / 128, 3), 256, GEMM_SMEM>>>(
        xh, xl, wqf, wkf, wvf, qbh, qbl, kf, vf, nullptr,
        /*onepass_mask=*/0b100, M, HIDDEN, HIDDEN);

    cudaFuncSetAttribute(attn_mma, cudaFuncAttributeMaxDynamicSharedMemorySize, ATTN_SMEM);
    attn_mma<<<dim3(BATCH * NHEADS, SEQ / QT), 256, ATTN_SMEM>>>(qbh, qbl, kf, vf, oh);

    // output projection: 1-pass (O single fp16), fp32 out
    gemm2<<<dim3(HIDDEN / 128, M / 128, 1), 256, GEMM_SMEM>>>(
        oh, oh, wof, wof, wof, nullptr, nullptr, nullptr, nullptr, out,
        /*onepass_mask=*/0b001, M, HIDDEN, HIDDEN);
}